// round 2
// baseline (speedup 1.0000x reference)
#include <cuda_runtime.h>
#include <math.h>

#define T_TOK 2048
#define DIM   1024
#define NEXP  8
#define FF    512
#define FSH   1024

// ---------------- scratch (__device__ globals: allocation-free) ----------------
__device__ int   g_count[NEXP];
__device__ int   g_tok[NEXP][T_TOK];
__device__ float g_w[NEXP][T_TOK];
__device__ float g_H [NEXP * T_TOK * FF];   // expert hidden (silu(g)*u), compact per expert
__device__ float g_Hs[T_TOK * FSH];         // shared-expert hidden

__device__ __forceinline__ float silu_f(float v) {
    return v / (1.f + __expf(-v));
}

// ---------------- init: zero per-expert counters (runs every replay) ----------------
__global__ void k_init() {
    if (threadIdx.x < NEXP) g_count[threadIdx.x] = 0;
}

// ---------------- router: logits, top-2, softmax, bucket append ----------------
__global__ void k_router(const float* __restrict__ x, const float* __restrict__ Wr,
                         const float* __restrict__ bias) {
    int t    = blockIdx.x * blockDim.y + threadIdx.y;   // one warp per token
    int lane = threadIdx.x;
    const float* xr = x + (size_t)t * DIM;
    float acc[NEXP];
#pragma unroll
    for (int e = 0; e < NEXP; e++) acc[e] = 0.f;
    for (int d = lane; d < DIM; d += 32) {
        float xv = xr[d];
        const float* w = Wr + d * NEXP;
#pragma unroll
        for (int e = 0; e < NEXP; e++) acc[e] += xv * w[e];
    }
#pragma unroll
    for (int o = 16; o > 0; o >>= 1)
#pragma unroll
        for (int e = 0; e < NEXP; e++)
            acc[e] += __shfl_down_sync(0xffffffffu, acc[e], o);
    if (lane == 0) {
        float v[NEXP];
#pragma unroll
        for (int e = 0; e < NEXP; e++) v[e] = acc[e] + bias[e];
        // top-2, earliest-index tie-break (matches jax.lax.top_k)
        int i0 = 0;
#pragma unroll
        for (int e = 1; e < NEXP; e++) if (v[e] > v[i0]) i0 = e;
        int i1 = (i0 == 0) ? 1 : 0;
#pragma unroll
        for (int e = 0; e < NEXP; e++) if (e != i0 && v[e] > v[i1]) i1 = e;
        float e1    = __expf(v[i1] - v[i0]);
        float denom = 1.f + e1;
        float p0 = 1.f / denom, p1 = e1 / denom;
        int p = atomicAdd(&g_count[i0], 1);
        g_tok[i0][p] = t; g_w[i0][p] = p0;
        p = atomicAdd(&g_count[i1], 1);
        g_tok[i1][p] = t; g_w[i1][p] = p1;
    }
}

// ---------------- expert gate+up (gathered rows) -> g_H ----------------
// tile 64(M) x 64(N), BK=16, 256 threads, 4x4 microtile, gate & up fused
__global__ __launch_bounds__(256)
void k_expert_gateup(const float* __restrict__ x, const float* __restrict__ Wg,
                     const float* __restrict__ Wu) {
    const int e   = blockIdx.z;
    const int cnt = g_count[e];
    const int m0  = blockIdx.y * 64;
    if (m0 >= cnt) return;
    const int n0  = blockIdx.x * 64;

    __shared__ __align__(16) float Xs[16][68];
    __shared__ __align__(16) float Gs[16][64];
    __shared__ __align__(16) float Us[16][64];
    __shared__ int rows[64];

    const int tid = threadIdx.x;
    if (tid < 64) {
        int m = m0 + tid;
        rows[tid] = (m < cnt) ? g_tok[e][m] : -1;
    }
    __syncthreads();

    const int tx = tid & 15, ty = tid >> 4;          // microtile coords
    const int lm = tid >> 2, lk = (tid & 3) * 4;     // X-tile loader coords
    const int bk = tid >> 4, bn = (tid & 15) * 4;    // W-tile loader coords
    const float* Wge = Wg + (size_t)e * DIM * FF;
    const float* Wue = Wu + (size_t)e * DIM * FF;

    float ag[4][4] = {}, au[4][4] = {};
    const int r = rows[lm];

    for (int k0 = 0; k0 < DIM; k0 += 16) {
        float4 xv = make_float4(0.f, 0.f, 0.f, 0.f);
        if (r >= 0) xv = *(const float4*)(x + (size_t)r * DIM + k0 + lk);
        Xs[lk + 0][lm] = xv.x; Xs[lk + 1][lm] = xv.y;
        Xs[lk + 2][lm] = xv.z; Xs[lk + 3][lm] = xv.w;
        *(float4*)&Gs[bk][bn] = *(const float4*)(Wge + (size_t)(k0 + bk) * FF + n0 + bn);
        *(float4*)&Us[bk][bn] = *(const float4*)(Wue + (size_t)(k0 + bk) * FF + n0 + bn);
        __syncthreads();
#pragma unroll
        for (int kk = 0; kk < 16; kk++) {
            float4 a4 = *(const float4*)&Xs[kk][ty * 4];
            float4 g4 = *(const float4*)&Gs[kk][tx * 4];
            float4 u4 = *(const float4*)&Us[kk][tx * 4];
            float av[4] = {a4.x, a4.y, a4.z, a4.w};
            float gv[4] = {g4.x, g4.y, g4.z, g4.w};
            float uv[4] = {u4.x, u4.y, u4.z, u4.w};
#pragma unroll
            for (int i = 0; i < 4; i++)
#pragma unroll
                for (int j = 0; j < 4; j++) {
                    ag[i][j] = fmaf(av[i], gv[j], ag[i][j]);
                    au[i][j] = fmaf(av[i], uv[j], au[i][j]);
                }
        }
        __syncthreads();
    }
#pragma unroll
    for (int i = 0; i < 4; i++) {
        int m = m0 + ty * 4 + i;
        if (m < cnt) {
            float hv[4];
#pragma unroll
            for (int j = 0; j < 4; j++)
                hv[j] = silu_f(ag[i][j]) * au[i][j];
            *(float4*)(g_H + ((size_t)e * T_TOK + m) * FF + n0 + tx * 4) =
                make_float4(hv[0], hv[1], hv[2], hv[3]);
        }
    }
}

// ---------------- expert down: g_H @ Wd_e, weighted atomic scatter ----------------
__global__ __launch_bounds__(256)
void k_expert_down(const float* __restrict__ Wd, float* __restrict__ out) {
    const int e   = blockIdx.z;
    const int cnt = g_count[e];
    const int m0  = blockIdx.y * 64;
    if (m0 >= cnt) return;
    const int n0  = blockIdx.x * 64;

    __shared__ __align__(16) float As[16][68];
    __shared__ __align__(16) float Bs[16][64];

    const int tid = threadIdx.x;
    const int tx = tid & 15, ty = tid >> 4;
    const int lm = tid >> 2, lk = (tid & 3) * 4;
    const int bk = tid >> 4, bn = (tid & 15) * 4;
    const float* Wde = Wd + (size_t)e * FF * DIM;
    const float* He  = g_H + (size_t)e * T_TOK * FF;

    float acc[4][4] = {};
    const int  gm   = m0 + lm;
    const bool mval = (gm < cnt);

    for (int k0 = 0; k0 < FF; k0 += 16) {
        float4 av = make_float4(0.f, 0.f, 0.f, 0.f);
        if (mval) av = *(const float4*)(He + (size_t)gm * FF + k0 + lk);
        As[lk + 0][lm] = av.x; As[lk + 1][lm] = av.y;
        As[lk + 2][lm] = av.z; As[lk + 3][lm] = av.w;
        *(float4*)&Bs[bk][bn] = *(const float4*)(Wde + (size_t)(k0 + bk) * DIM + n0 + bn);
        __syncthreads();
#pragma unroll
        for (int kk = 0; kk < 16; kk++) {
            float4 a4 = *(const float4*)&As[kk][ty * 4];
            float4 b4 = *(const float4*)&Bs[kk][tx * 4];
            float av2[4] = {a4.x, a4.y, a4.z, a4.w};
            float bv2[4] = {b4.x, b4.y, b4.z, b4.w};
#pragma unroll
            for (int i = 0; i < 4; i++)
#pragma unroll
                for (int j = 0; j < 4; j++)
                    acc[i][j] = fmaf(av2[i], bv2[j], acc[i][j]);
        }
        __syncthreads();
    }
#pragma unroll
    for (int i = 0; i < 4; i++) {
        int m = m0 + ty * 4 + i;
        if (m < cnt) {
            int   t = g_tok[e][m];
            float w = g_w[e][m];
            float* op = out + (size_t)t * DIM + n0 + tx * 4;
#pragma unroll
            for (int j = 0; j < 4; j++)
                atomicAdd(op + j, w * acc[i][j]);
        }
    }
}

// ---------------- shared expert gate+up (dense) -> g_Hs ----------------
__global__ __launch_bounds__(256)
void k_shared_gateup(const float* __restrict__ x, const float* __restrict__ Sg,
                     const float* __restrict__ Su) {
    const int m0 = blockIdx.y * 64;
    const int n0 = blockIdx.x * 64;

    __shared__ __align__(16) float Xs[16][68];
    __shared__ __align__(16) float Gs[16][64];
    __shared__ __align__(16) float Us[16][64];

    const int tid = threadIdx.x;
    const int tx = tid & 15, ty = tid >> 4;
    const int lm = tid >> 2, lk = (tid & 3) * 4;
    const int bk = tid >> 4, bn = (tid & 15) * 4;

    float ag[4][4] = {}, au[4][4] = {};
    const int gm = m0 + lm;

    for (int k0 = 0; k0 < DIM; k0 += 16) {
        float4 xv = *(const float4*)(x + (size_t)gm * DIM + k0 + lk);
        Xs[lk + 0][lm] = xv.x; Xs[lk + 1][lm] = xv.y;
        Xs[lk + 2][lm] = xv.z; Xs[lk + 3][lm] = xv.w;
        *(float4*)&Gs[bk][bn] = *(const float4*)(Sg + (size_t)(k0 + bk) * FSH + n0 + bn);
        *(float4*)&Us[bk][bn] = *(const float4*)(Su + (size_t)(k0 + bk) * FSH + n0 + bn);
        __syncthreads();
#pragma unroll
        for (int kk = 0; kk < 16; kk++) {
            float4 a4 = *(const float4*)&Xs[kk][ty * 4];
            float4 g4 = *(const float4*)&Gs[kk][tx * 4];
            float4 u4 = *(const float4*)&Us[kk][tx * 4];
            float av[4] = {a4.x, a4.y, a4.z, a4.w};
            float gv[4] = {g4.x, g4.y, g4.z, g4.w};
            float uv[4] = {u4.x, u4.y, u4.z, u4.w};
#pragma unroll
            for (int i = 0; i < 4; i++)
#pragma unroll
                for (int j = 0; j < 4; j++) {
                    ag[i][j] = fmaf(av[i], gv[j], ag[i][j]);
                    au[i][j] = fmaf(av[i], uv[j], au[i][j]);
                }
        }
        __syncthreads();
    }
#pragma unroll
    for (int i = 0; i < 4; i++) {
        int m = m0 + ty * 4 + i;
        float hv[4];
#pragma unroll
        for (int j = 0; j < 4; j++)
            hv[j] = silu_f(ag[i][j]) * au[i][j];
        *(float4*)(g_Hs + (size_t)m * FSH + n0 + tx * 4) =
            make_float4(hv[0], hv[1], hv[2], hv[3]);
    }
}

// ---------------- shared expert down: writes the FULL output (first) ----------------
__global__ __launch_bounds__(256)
void k_shared_down(const float* __restrict__ Sd, float* __restrict__ out) {
    const int m0 = blockIdx.y * 64;
    const int n0 = blockIdx.x * 64;

    __shared__ __align__(16) float As[16][68];
    __shared__ __align__(16) float Bs[16][64];

    const int tid = threadIdx.x;
    const int tx = tid & 15, ty = tid >> 4;
    const int lm = tid >> 2, lk = (tid & 3) * 4;
    const int bk = tid >> 4, bn = (tid & 15) * 4;

    float acc[4][4] = {};
    const int gm = m0 + lm;

    for (int k0 = 0; k0 < FSH; k0 += 16) {
        float4 av = *(const float4*)(g_Hs + (size_t)gm * FSH + k0 + lk);
        As[lk + 0][lm] = av.x; As[lk + 1][lm] = av.y;
        As[lk + 2][lm] = av.z; As[lk + 3][lm] = av.w;
        *(float4*)&Bs[bk][bn] = *(const float4*)(Sd + (size_t)(k0 + bk) * DIM + n0 + bn);
        __syncthreads();
#pragma unroll
        for (int kk = 0; kk < 16; kk++) {
            float4 a4 = *(const float4*)&As[kk][ty * 4];
            float4 b4 = *(const float4*)&Bs[kk][tx * 4];
            float av2[4] = {a4.x, a4.y, a4.z, a4.w};
            float bv2[4] = {b4.x, b4.y, b4.z, b4.w};
#pragma unroll
            for (int i = 0; i < 4; i++)
#pragma unroll
                for (int j = 0; j < 4; j++)
                    acc[i][j] = fmaf(av2[i], bv2[j], acc[i][j]);
        }
        __syncthreads();
    }
#pragma unroll
    for (int i = 0; i < 4; i++) {
        int m = m0 + ty * 4 + i;
        *(float4*)(out + (size_t)m * DIM + n0 + tx * 4) =
            make_float4(acc[i][0], acc[i][1], acc[i][2], acc[i][3]);
    }
}

// ---------------- launch ----------------
extern "C" void kernel_launch(void* const* d_in, const int* in_sizes, int n_in,
                              void* d_out, int out_size) {
    const float* x    = (const float*)d_in[0];
    const float* Wr   = (const float*)d_in[1];
    const float* Wg   = (const float*)d_in[2];
    const float* Wu   = (const float*)d_in[3];
    const float* Wd   = (const float*)d_in[4];
    const float* Sg   = (const float*)d_in[5];
    const float* Su   = (const float*)d_in[6];
    const float* Sd   = (const float*)d_in[7];
    const float* bias = (const float*)d_in[8];
    float* out = (float*)d_out;

    k_init<<<1, 32>>>();
    {
        dim3 rb(32, 8);
        k_router<<<T_TOK / 8, rb>>>(x, Wr, bias);
    }
    // shared expert (writes full out), then routed experts (atomic adds on top)
    k_shared_gateup<<<dim3(FSH / 64, T_TOK / 64), 256>>>(x, Sg, Su);
    k_shared_down  <<<dim3(DIM / 64, T_TOK / 64), 256>>>(Sd, out);
    k_expert_gateup<<<dim3(FF  / 64, T_TOK / 64, NEXP), 256>>>(x, Wg, Wu);
    k_expert_down  <<<dim3(DIM / 64, T_TOK / 64, NEXP), 256>>>(Wd, out);
}

// round 3
// speedup vs baseline: 2.5707x; 2.5707x over previous
#include <cuda_runtime.h>
#include <math.h>
#include <stdint.h>

#define T_TOK 2048
#define DIM   1024
#define NEXP  8
#define FF    512
#define FSH   1024

// ---------------- scratch (__device__ globals: allocation-free) ----------------
__device__ int   g_count[NEXP];
__device__ int   g_tok[NEXP][T_TOK];
__device__ float g_w[NEXP][T_TOK];
__device__ float g_G [NEXP * T_TOK * FF];   // routed gate pre-act
__device__ float g_U [NEXP * T_TOK * FF];   // routed up
__device__ float g_H [NEXP * T_TOK * FF];   // routed hidden silu(g)*u
__device__ float g_Gs[T_TOK * FSH];
__device__ float g_Us[T_TOK * FSH];
__device__ float g_Hs[T_TOK * FSH];

__device__ __forceinline__ float silu_f(float v) {
    return v / (1.f + __expf(-v));
}

__device__ __forceinline__ uint32_t f2tf32(float f) {
    uint32_t u;
    asm("cvt.rna.tf32.f32 %0, %1;" : "=r"(u) : "f"(f));
    return u;
}

__device__ __forceinline__ void mma_tf32(float4& c, const uint32_t a[4], const uint32_t b[2]) {
    asm volatile(
        "mma.sync.aligned.m16n8k8.row.col.f32.tf32.tf32.f32 "
        "{%0,%1,%2,%3}, {%4,%5,%6,%7}, {%8,%9}, {%0,%1,%2,%3};"
        : "+f"(c.x), "+f"(c.y), "+f"(c.z), "+f"(c.w)
        : "r"(a[0]), "r"(a[1]), "r"(a[2]), "r"(a[3]), "r"(b[0]), "r"(b[1]));
}

// ---------------- init ----------------
__global__ void k_init() {
    if (threadIdx.x < NEXP) g_count[threadIdx.x] = 0;
}

// ---------------- router (fp32 exact) ----------------
__global__ void k_router(const float* __restrict__ x, const float* __restrict__ Wr,
                         const float* __restrict__ bias) {
    int t    = blockIdx.x * blockDim.y + threadIdx.y;
    int lane = threadIdx.x;
    const float* xr = x + (size_t)t * DIM;
    float acc[NEXP];
#pragma unroll
    for (int e = 0; e < NEXP; e++) acc[e] = 0.f;
    for (int d = lane; d < DIM; d += 32) {
        float xv = xr[d];
        const float* w = Wr + d * NEXP;
#pragma unroll
        for (int e = 0; e < NEXP; e++) acc[e] += xv * w[e];
    }
#pragma unroll
    for (int o = 16; o > 0; o >>= 1)
#pragma unroll
        for (int e = 0; e < NEXP; e++)
            acc[e] += __shfl_down_sync(0xffffffffu, acc[e], o);
    if (lane == 0) {
        float v[NEXP];
#pragma unroll
        for (int e = 0; e < NEXP; e++) v[e] = acc[e] + bias[e];
        int i0 = 0;
#pragma unroll
        for (int e = 1; e < NEXP; e++) if (v[e] > v[i0]) i0 = e;
        int i1 = (i0 == 0) ? 1 : 0;
#pragma unroll
        for (int e = 0; e < NEXP; e++) if (e != i0 && v[e] > v[i1]) i1 = e;
        float e1    = __expf(v[i1] - v[i0]);
        float denom = 1.f + e1;
        float p0 = 1.f / denom, p1 = e1 / denom;
        int p = atomicAdd(&g_count[i0], 1);
        g_tok[i0][p] = t; g_w[i0][p] = p0;
        p = atomicAdd(&g_count[i1], 1);
        g_tok[i1][p] = t; g_w[i1][p] = p1;
    }
}

// =====================================================================
// tf32 tensor-core GEMM core: 128x128 block tile, BK=16, 8 warps (64x32 each)
// A [M,K] row-major (optionally row-gathered), B [K,N] row-major.
// EPI 0: C[m,n] = acc (m is compact index)
// EPI 1: atomicAdd(C[tok[m], n], w[m]*acc)
// =====================================================================
#define SPAD 136   // smem row stride (8-float pad -> conflict-free frag reads)

template<int EPI>
__device__ __forceinline__ void gemm_core(
    const float* __restrict__ Abase, const int* __restrict__ rowsA, int lda,
    const float* __restrict__ B, int ldb,
    float* __restrict__ C, int ldc,
    int Mcnt, int K,
    const int* __restrict__ tokv, const float* __restrict__ wv)
{
    const int m0 = blockIdx.y * 128;
    if (m0 >= Mcnt) return;
    const int n0 = blockIdx.x * 128;

    __shared__ __align__(16) float As[16 * SPAD];
    __shared__ __align__(16) float Bs[16 * SPAD];

    const int tid  = threadIdx.x;
    const int lane = tid & 31;
    const int w    = tid >> 5;
    const int wm   = w >> 2;      // 0..1
    const int wn   = w & 3;       // 0..3

    // ---- A loader: thread covers row am, k-chunk of 8 ----
    const int am  = tid >> 1;           // 0..127
    const int aj  = tid & 1;            // 0..1 (which 8-wide k chunk)
    const int amg = m0 + am;
    const bool aval = (amg < Mcnt);
    const float* Arow = Abase;
    if (aval) {
        int r = rowsA ? rowsA[amg] : amg;
        Arow = Abase + (size_t)r * lda;
    }
    // ---- B loader: thread covers k-row bk, 8 consecutive n ----
    const int bk  = tid >> 4;           // 0..15
    const int bnt = tid & 15;           // 0..15
    const float* Bptr = B + (size_t)bk * ldb + n0 + bnt * 8;
    float* BsRow = &Bs[bk * SPAD + bnt * 8];

    float4 acc[4][4];
#pragma unroll
    for (int i = 0; i < 4; i++)
#pragma unroll
        for (int j = 0; j < 4; j++) acc[i][j] = make_float4(0.f, 0.f, 0.f, 0.f);

    const int fk = lane & 3;       // fragment k within 4
    const int fr = lane >> 2;      // fragment row/col within 8

    for (int k0 = 0; k0 < K; k0 += 16) {
        // stage A (row am, k in [k0+8*aj, +8)), tf32-rounded, layout As[k][m]
        {
            float va[8];
            if (aval) {
                float4 t0 = *(const float4*)(Arow + k0 + aj * 8);
                float4 t1 = *(const float4*)(Arow + k0 + aj * 8 + 4);
                va[0] = t0.x; va[1] = t0.y; va[2] = t0.z; va[3] = t0.w;
                va[4] = t1.x; va[5] = t1.y; va[6] = t1.z; va[7] = t1.w;
            } else {
#pragma unroll
                for (int c = 0; c < 8; c++) va[c] = 0.f;
            }
#pragma unroll
            for (int c = 0; c < 8; c++)
                As[(aj * 8 + c) * SPAD + am] = __uint_as_float(f2tf32(va[c]));
        }
        // stage B (k-row bk, n in [n0+8*bnt, +8)), layout Bs[k][n]
        {
            float4 t0 = *(const float4*)(Bptr + (size_t)k0 * ldb);
            float4 t1 = *(const float4*)(Bptr + (size_t)k0 * ldb + 4);
            float vb[8] = {t0.x, t0.y, t0.z, t0.w, t1.x, t1.y, t1.z, t1.w};
#pragma unroll
            for (int c = 0; c < 8; c++)
                BsRow[c] = __uint_as_float(f2tf32(vb[c]));
        }
        __syncthreads();

#pragma unroll
        for (int ks = 0; ks < 2; ks++) {
            const int kb = ks * 8 + fk;
            uint32_t a[4][4], b[4][2];
#pragma unroll
            for (int i = 0; i < 4; i++) {
                const int m = wm * 64 + i * 16 + fr;
                a[i][0] = __float_as_uint(As[kb * SPAD + m]);
                a[i][1] = __float_as_uint(As[kb * SPAD + m + 8]);
                a[i][2] = __float_as_uint(As[(kb + 4) * SPAD + m]);
                a[i][3] = __float_as_uint(As[(kb + 4) * SPAD + m + 8]);
            }
#pragma unroll
            for (int j = 0; j < 4; j++) {
                const int n = wn * 32 + j * 8 + fr;
                b[j][0] = __float_as_uint(Bs[kb * SPAD + n]);
                b[j][1] = __float_as_uint(Bs[(kb + 4) * SPAD + n]);
            }
#pragma unroll
            for (int i = 0; i < 4; i++)
#pragma unroll
                for (int j = 0; j < 4; j++)
                    mma_tf32(acc[i][j], a[i], b[j]);
        }
        __syncthreads();
    }

    // ---- epilogue ----
    const int er = lane >> 2;
    const int ec = (lane & 3) * 2;
#pragma unroll
    for (int i = 0; i < 4; i++) {
        const int ml0 = wm * 64 + i * 16 + er;
        const int mg0 = m0 + ml0;
        const int mg1 = mg0 + 8;
#pragma unroll
        for (int j = 0; j < 4; j++) {
            const int n = n0 + wn * 32 + j * 8 + ec;
            if (EPI == 0) {
                if (mg0 < Mcnt)
                    *(float2*)&C[(size_t)mg0 * ldc + n] = make_float2(acc[i][j].x, acc[i][j].y);
                if (mg1 < Mcnt)
                    *(float2*)&C[(size_t)mg1 * ldc + n] = make_float2(acc[i][j].z, acc[i][j].w);
            } else {
                if (mg0 < Mcnt) {
                    int   t  = tokv[mg0];
                    float wg = wv[mg0];
                    atomicAdd(&C[(size_t)t * ldc + n],     wg * acc[i][j].x);
                    atomicAdd(&C[(size_t)t * ldc + n + 1], wg * acc[i][j].y);
                }
                if (mg1 < Mcnt) {
                    int   t  = tokv[mg1];
                    float wg = wv[mg1];
                    atomicAdd(&C[(size_t)t * ldc + n],     wg * acc[i][j].z);
                    atomicAdd(&C[(size_t)t * ldc + n + 1], wg * acc[i][j].w);
                }
            }
        }
    }
}

// ---------------- GEMM wrappers ----------------
// routed gate/up: z = e*2 + mat
__global__ __launch_bounds__(256, 2)
void k_moe_gateup(const float* __restrict__ x, const float* __restrict__ Wg,
                  const float* __restrict__ Wu) {
    const int z = blockIdx.z, e = z >> 1, mat = z & 1;
    const float* B = (mat ? Wu : Wg) + (size_t)e * DIM * FF;
    float*       C = (mat ? g_U : g_G) + (size_t)e * T_TOK * FF;
    gemm_core<0>(x, g_tok[e], DIM, B, FF, C, FF, g_count[e], DIM, nullptr, nullptr);
}

__global__ __launch_bounds__(256, 2)
void k_moe_down(const float* __restrict__ Wd, float* __restrict__ out) {
    const int e = blockIdx.z;
    gemm_core<1>(g_H + (size_t)e * T_TOK * FF, nullptr, FF,
                 Wd + (size_t)e * FF * DIM, DIM,
                 out, DIM, g_count[e], FF, g_tok[e], g_w[e]);
}

__global__ __launch_bounds__(256, 2)
void k_sh_gateup(const float* __restrict__ x, const float* __restrict__ Sg,
                 const float* __restrict__ Su) {
    const int mat = blockIdx.z;
    gemm_core<0>(x, nullptr, DIM, mat ? Su : Sg, FSH,
                 mat ? g_Us : g_Gs, FSH, T_TOK, DIM, nullptr, nullptr);
}

__global__ __launch_bounds__(256, 2)
void k_sh_down(const float* __restrict__ Sd, float* __restrict__ out) {
    gemm_core<0>(g_Hs, nullptr, FSH, Sd, DIM, out, DIM, T_TOK, FSH, nullptr, nullptr);
}

// ---------------- elementwise silu*up ----------------
__global__ void k_moe_silu() {
    const int e = blockIdx.y;
    const int total = g_count[e] * FF;
    const int idx = (blockIdx.x * 256 + threadIdx.x) * 4;
    if (idx >= total) return;
    const size_t base = (size_t)e * T_TOK * FF + idx;
    float4 g4 = *(const float4*)&g_G[base];
    float4 u4 = *(const float4*)&g_U[base];
    float4 h;
    h.x = silu_f(g4.x) * u4.x;
    h.y = silu_f(g4.y) * u4.y;
    h.z = silu_f(g4.z) * u4.z;
    h.w = silu_f(g4.w) * u4.w;
    *(float4*)&g_H[base] = h;
}

__global__ void k_sh_silu() {
    const size_t idx = ((size_t)blockIdx.x * 256 + threadIdx.x) * 4;
    float4 g4 = *(const float4*)&g_Gs[idx];
    float4 u4 = *(const float4*)&g_Us[idx];
    float4 h;
    h.x = silu_f(g4.x) * u4.x;
    h.y = silu_f(g4.y) * u4.y;
    h.z = silu_f(g4.z) * u4.z;
    h.w = silu_f(g4.w) * u4.w;
    *(float4*)&g_Hs[idx] = h;
}

// ---------------- launch ----------------
extern "C" void kernel_launch(void* const* d_in, const int* in_sizes, int n_in,
                              void* d_out, int out_size) {
    const float* x    = (const float*)d_in[0];
    const float* Wr   = (const float*)d_in[1];
    const float* Wg   = (const float*)d_in[2];
    const float* Wu   = (const float*)d_in[3];
    const float* Wd   = (const float*)d_in[4];
    const float* Sg   = (const float*)d_in[5];
    const float* Su   = (const float*)d_in[6];
    const float* Sd   = (const float*)d_in[7];
    const float* bias = (const float*)d_in[8];
    float* out = (float*)d_out;

    k_init<<<1, 32>>>();
    k_router<<<T_TOK / 8, dim3(32, 8)>>>(x, Wr, bias);

    // shared expert: dense GEMMs; down writes the full output (poisoned buffer)
    k_sh_gateup<<<dim3(FSH / 128, T_TOK / 128, 2), 256>>>(x, Sg, Su);
    k_sh_silu  <<<(T_TOK * FSH) / 1024, 256>>>();
    k_sh_down  <<<dim3(DIM / 128, T_TOK / 128), 256>>>(Sd, out);

    // routed experts: sparse gather GEMMs, atomic scatter on top of shared out
    k_moe_gateup<<<dim3(FF / 128, T_TOK / 128, NEXP * 2), 256>>>(x, Wg, Wu);
    k_moe_silu  <<<dim3((T_TOK * FF) / 1024, NEXP), 256>>>();
    k_moe_down  <<<dim3(DIM / 128, T_TOK / 128, NEXP), 256>>>(Wd, out);
}